// round 9
// baseline (speedup 1.0000x reference)
#include <cuda_runtime.h>
#include <math.h>

#define NB    4
#define NCH   256
#define FH    38
#define FW    38
#define HW    (FH * FW)            // 1444
#define PH    7
#define PW    7
#define SCALE 0.0625f
#define BINS  (PH * PW)            // 49
#define TOTAL (NCH * BINS)         // 12544
#define CG    32                   // channels per block
#define NCGRP (NCH / CG)           // 8

// Scratch: feat transposed to (B, H*W, C) so lane=channel loads are coalesced.
__device__ float g_feat_t[NB * HW * NCH];

__global__ __launch_bounds__(256) void transpose_kernel(const float* __restrict__ feat)
{
    __shared__ float tile[32][33];
    const int b   = blockIdx.z;
    const int hw0 = blockIdx.x * 32;
    const int c0  = blockIdx.y * 32;
    const int tx  = threadIdx.x;     // 0..31
    const int ty  = threadIdx.y;     // 0..7

    const float* src = feat + b * NCH * HW;
#pragma unroll
    for (int i = 0; i < 4; ++i) {
        int c  = c0 + ty + i * 8;
        int hw = hw0 + tx;
        tile[ty + i * 8][tx] = (hw < HW) ? src[c * HW + hw] : 0.0f;
    }
    __syncthreads();
    float* dst = g_feat_t + b * HW * NCH;
#pragma unroll
    for (int i = 0; i < 4; ++i) {
        int hw = hw0 + ty + i * 8;
        int c  = c0 + tx;
        if (hw < HW) dst[hw * NCH + c] = tile[tx][ty + i * 8];
    }
}

__global__ __launch_bounds__(256) void roipool2_kernel(
    const float* __restrict__ rois,
    const int*   __restrict__ roib,
    float*       __restrict__ out)
{
    const int n    = blockIdx.y;
    const int c0   = blockIdx.x * CG;
    const int t    = threadIdx.x;
    const int wid  = t >> 5;
    const int lane = t & 31;

    __shared__ int4  sb[BINS];          // (h0, h1, w0, w1) per bin
    __shared__ int   bofs;
    __shared__ float so[CG * BINS];     // [c_local][bin], stride 49 (odd -> no conflicts)

    if (t < BINS) {
        // Boundary math matches XLA-CPU fast-math reference bit-for-bit:
        // exact IEEE ops EXCEPT division lowered as x * rn(1/7).
        const float R7 = 1.0f / 7.0f;
        float x1 = floorf(__fadd_rn(__fmul_rn(rois[n * 4 + 0], SCALE), 0.5f));
        float y1 = floorf(__fadd_rn(__fmul_rn(rois[n * 4 + 1], SCALE), 0.5f));
        float x2 = floorf(__fadd_rn(__fmul_rn(rois[n * 4 + 2], SCALE), 0.5f));
        float y2 = floorf(__fadd_rn(__fmul_rn(rois[n * 4 + 3], SCALE), 0.5f));
        float roi_w = fmaxf(__fadd_rn(__fsub_rn(x2, x1), 1.0f), 1.0f);
        float roi_h = fmaxf(__fadd_rn(__fsub_rn(y2, y1), 1.0f), 1.0f);
        float bin_h = __fmul_rn(roi_h, R7);
        float bin_w = __fmul_rn(roi_w, R7);

        int ph = t / PW;
        int pw = t - ph * PW;
        float fph = (float)ph, fpw = (float)pw;

        int h0 = (int)fminf(fmaxf(__fadd_rn(floorf(__fmul_rn(fph, bin_h)), y1), 0.0f), (float)FH);
        int h1 = (int)fminf(fmaxf(__fadd_rn(ceilf(__fmul_rn(__fadd_rn(fph, 1.0f), bin_h)), y1), 0.0f), (float)FH);
        int w0 = (int)fminf(fmaxf(__fadd_rn(floorf(__fmul_rn(fpw, bin_w)), x1), 0.0f), (float)FW);
        int w1 = (int)fminf(fmaxf(__fadd_rn(ceilf(__fmul_rn(__fadd_rn(fpw, 1.0f), bin_w)), x1), 0.0f), (float)FW);

        sb[t] = make_int4(h0, h1, w0, w1);
        if (t == 0) bofs = roib[n] * (HW * NCH);
    }
    __syncthreads();

    // lane = channel; bin bounds warp-uniform -> uniform branches, coalesced loads.
    const float* __restrict__ fb = g_feat_t + bofs + c0 + lane;

    for (int bin = wid; bin < BINS; bin += 8) {
        const int4 bb = sb[bin];              // broadcast
        const int h0 = bb.x, h1 = bb.y, w0 = bb.z, w1 = bb.w;
        float m;
        if (h0 < h1 && w0 < w1) {
            m = -INFINITY;
            for (int h = h0; h < h1; ++h) {
                const float* rowp = fb + (h * FW + w0) * NCH;
                for (int w = w0; w < w1; ++w) {
                    m = fmaxf(m, *rowp);
                    rowp += NCH;
                }
            }
        } else {
            m = 0.0f;                         // empty bin -> 0 per reference
        }
        so[lane * BINS + bin] = m;
    }
    __syncthreads();

    // Block's output region is contiguous: fully coalesced flush.
    float* __restrict__ op = out + n * TOTAL + c0 * BINS;
#pragma unroll
    for (int e = t; e < CG * BINS; e += 256)
        op[e] = so[e];
}

extern "C" void kernel_launch(void* const* d_in, const int* in_sizes, int n_in,
                              void* d_out, int out_size)
{
    const float* feat = (const float*)d_in[0];
    const float* rois = (const float*)d_in[1];
    const int*   rb   = (const int*)d_in[2];
    float*       out  = (float*)d_out;

    dim3 tg((HW + 31) / 32, NCH / 32, NB);   // (46, 8, 4)
    dim3 tb(32, 8);
    transpose_kernel<<<tg, tb>>>(feat);

    dim3 grid(NCGRP, 256);                   // (8, 256)
    roipool2_kernel<<<grid, 256>>>(rois, rb, out);
}

// round 10
// speedup vs baseline: 1.4307x; 1.4307x over previous
#include <cuda_runtime.h>
#include <math.h>

#define NB    4
#define NCH   256
#define FH    38
#define FW    38
#define HW    (FH * FW)            // 1444
#define PH    7
#define PW    7
#define SCALE 0.0625f
#define BINS  (PH * PW)            // 49
#define TOTAL (NCH * BINS)         // 12544
#define CG    32                   // channels per block (one lane each)
#define NCGRP (NCH / CG)           // 8

// Scratch: feat transposed to (B, H*W, C) so lane=channel loads are coalesced.
__device__ float g_feat_t[NB * HW * NCH];

__global__ __launch_bounds__(256) void transpose_kernel(const float* __restrict__ feat)
{
    __shared__ float tile[32][33];
    const int b   = blockIdx.z;
    const int hw0 = blockIdx.x * 32;
    const int c0  = blockIdx.y * 32;
    const int tx  = threadIdx.x;     // 0..31
    const int ty  = threadIdx.y;     // 0..7

    const float* src = feat + b * NCH * HW;
#pragma unroll
    for (int i = 0; i < 4; ++i) {
        int c  = c0 + ty + i * 8;
        int hw = hw0 + tx;
        tile[ty + i * 8][tx] = (hw < HW) ? src[c * HW + hw] : 0.0f;
    }
    __syncthreads();
    float* dst = g_feat_t + b * HW * NCH;
#pragma unroll
    for (int i = 0; i < 4; ++i) {
        int hw = hw0 + ty + i * 8;
        int c  = c0 + tx;
        if (hw < HW) dst[hw * NCH + c] = tile[tx][ty + i * 8];
    }
}

__global__ __launch_bounds__(256) void roipool2_kernel(
    const float* __restrict__ rois,
    const int*   __restrict__ roib,
    float*       __restrict__ out)
{
    const int n    = blockIdx.y;
    const int c0   = blockIdx.x * CG;
    const int t    = threadIdx.x;
    const int wid  = t >> 5;
    const int lane = t & 31;

    __shared__ int      sbinoff[BINS];   // (h0*FW + w0) * NCH, element offset
    __shared__ unsigned smask[BINS];     // 4x4 validity bitmask (spans <= 4 here)
    __shared__ int      bofs;
    __shared__ float    so[CG * BINS];   // [c_local][bin], stride 49 -> conflict-free

    if (t < BINS) {
        // Boundary math matches XLA-CPU fast-math reference bit-for-bit:
        // exact IEEE ops EXCEPT division lowered as x * rn(1/7).
        const float R7 = 1.0f / 7.0f;
        float x1 = floorf(__fadd_rn(__fmul_rn(rois[n * 4 + 0], SCALE), 0.5f));
        float y1 = floorf(__fadd_rn(__fmul_rn(rois[n * 4 + 1], SCALE), 0.5f));
        float x2 = floorf(__fadd_rn(__fmul_rn(rois[n * 4 + 2], SCALE), 0.5f));
        float y2 = floorf(__fadd_rn(__fmul_rn(rois[n * 4 + 3], SCALE), 0.5f));
        float roi_w = fmaxf(__fadd_rn(__fsub_rn(x2, x1), 1.0f), 1.0f);
        float roi_h = fmaxf(__fadd_rn(__fsub_rn(y2, y1), 1.0f), 1.0f);
        float bin_h = __fmul_rn(roi_h, R7);
        float bin_w = __fmul_rn(roi_w, R7);

        int ph = t / PW;
        int pw = t - ph * PW;
        float fph = (float)ph, fpw = (float)pw;

        int h0 = (int)fminf(fmaxf(__fadd_rn(floorf(__fmul_rn(fph, bin_h)), y1), 0.0f), (float)FH);
        int h1 = (int)fminf(fmaxf(__fadd_rn(ceilf(__fmul_rn(__fadd_rn(fph, 1.0f), bin_h)), y1), 0.0f), (float)FH);
        int w0 = (int)fminf(fmaxf(__fadd_rn(floorf(__fmul_rn(fpw, bin_w)), x1), 0.0f), (float)FW);
        int w1 = (int)fminf(fmaxf(__fadd_rn(ceilf(__fmul_rn(__fadd_rn(fpw, 1.0f), bin_w)), x1), 0.0f), (float)FW);

        unsigned mh = 0, mw = 0;
#pragma unroll
        for (int d = 0; d < 4; ++d) {
            mh |= (h0 + d < h1) ? (1u << d) : 0u;
            mw |= (w0 + d < w1) ? (1u << d) : 0u;
        }
        unsigned mask = 0;
#pragma unroll
        for (int d = 0; d < 4; ++d)
            mask |= ((mh >> d) & 1u) ? (mw << (4 * d)) : 0u;

        sbinoff[t] = (h0 * FW + w0) * NCH;
        smask[t]   = mask;
        if (t == 0) bofs = roib[n] * (HW * NCH);
    }
    __syncthreads();

    // lane = channel. Bin data warp-uniform; 16 independent candidate loads
    // at compile-time-constant offsets, uniform-predicated (no divergence,
    // disabled elements issue no memory). High MLP, coalesced 4-sector loads.
    const float* __restrict__ fb = g_feat_t + bofs + c0 + lane;

    for (int bin = wid; bin < BINS; bin += 8) {
        const unsigned mask = smask[bin];
        const float* __restrict__ f = fb + sbinoff[bin];
        float m = -INFINITY;
#pragma unroll
        for (int dh = 0; dh < 4; ++dh) {
#pragma unroll
            for (int dw = 0; dw < 4; ++dw) {
                if (mask & (1u << (dh * 4 + dw)))
                    m = fmaxf(m, f[(dh * FW + dw) * NCH]);
            }
        }
        if (m == -INFINITY) m = 0.0f;   // empty bin -> 0 per reference
        so[lane * BINS + bin] = m;
    }
    __syncthreads();

    // Block's output region is contiguous: fully coalesced flush.
    float* __restrict__ op = out + n * TOTAL + c0 * BINS;
#pragma unroll
    for (int e = t; e < CG * BINS; e += 256)
        op[e] = so[e];
}

extern "C" void kernel_launch(void* const* d_in, const int* in_sizes, int n_in,
                              void* d_out, int out_size)
{
    const float* feat = (const float*)d_in[0];
    const float* rois = (const float*)d_in[1];
    const int*   rb   = (const int*)d_in[2];
    float*       out  = (float*)d_out;

    dim3 tg((HW + 31) / 32, NCH / 32, NB);   // (46, 8, 4)
    dim3 tb(32, 8);
    transpose_kernel<<<tg, tb>>>(feat);

    dim3 grid(NCGRP, 256);                   // (8, 256)
    roipool2_kernel<<<grid, 256>>>(rois, rb, out);
}

// round 12
// speedup vs baseline: 1.6231x; 1.1345x over previous
#include <cuda_runtime.h>
#include <math.h>

#define NB    4
#define NCH   256
#define FH    38
#define FW    38
#define HW    (FH * FW)            // 1444
#define PH    7
#define PW    7
#define SCALE 0.0625f
#define BINS  (PH * PW)            // 49
#define TOTAL (NCH * BINS)         // 12544
#define CG    128                  // channels per block (lane covers 4 via float4)
#define NCGRP (NCH / CG)           // 2

// Scratch: feat transposed to (B, H*W, C). Declared as float4 so the base is
// 16B-aligned for vector loads in the pooling kernel.
__device__ float4 g_feat_t4[NB * HW * NCH / 4];

__global__ __launch_bounds__(256) void transpose_kernel(const float* __restrict__ feat)
{
    __shared__ float tile[32][33];
    const int b   = blockIdx.z;
    const int hw0 = blockIdx.x * 32;
    const int c0  = blockIdx.y * 32;
    const int tx  = threadIdx.x;     // 0..31
    const int ty  = threadIdx.y;     // 0..7

    const float* src = feat + b * NCH * HW;
#pragma unroll
    for (int i = 0; i < 4; ++i) {
        int c  = c0 + ty + i * 8;
        int hw = hw0 + tx;
        tile[ty + i * 8][tx] = (hw < HW) ? src[c * HW + hw] : 0.0f;
    }
    __syncthreads();
    float* dst = (float*)g_feat_t4 + b * HW * NCH;
#pragma unroll
    for (int i = 0; i < 4; ++i) {
        int hw = hw0 + ty + i * 8;
        int c  = c0 + tx;
        if (hw < HW) dst[hw * NCH + c] = tile[tx][ty + i * 8];
    }
}

__global__ __launch_bounds__(256) void roipool2_kernel(
    const float* __restrict__ rois,
    const int*   __restrict__ roib,
    float*       __restrict__ out)
{
    const int n    = blockIdx.y;
    const int c0   = blockIdx.x * CG;
    const int t    = threadIdx.x;
    const int wid  = t >> 5;
    const int lane = t & 31;

    __shared__ int      sbinoff4[BINS];  // (h0*FW + w0) * NCH/4, float4 offset
    __shared__ unsigned smask[BINS];     // 4x4 validity bitmask (spans <= 4 here)
    __shared__ int      bofs4;           // batch offset in float4 units
    __shared__ __align__(16) float so[CG * BINS];   // [c_local][bin]

    if (t < BINS) {
        // Boundary math matches XLA-CPU fast-math reference bit-for-bit:
        // exact IEEE ops EXCEPT division lowered as x * rn(1/7).
        const float R7 = 1.0f / 7.0f;
        float x1 = floorf(__fadd_rn(__fmul_rn(rois[n * 4 + 0], SCALE), 0.5f));
        float y1 = floorf(__fadd_rn(__fmul_rn(rois[n * 4 + 1], SCALE), 0.5f));
        float x2 = floorf(__fadd_rn(__fmul_rn(rois[n * 4 + 2], SCALE), 0.5f));
        float y2 = floorf(__fadd_rn(__fmul_rn(rois[n * 4 + 3], SCALE), 0.5f));
        float roi_w = fmaxf(__fadd_rn(__fsub_rn(x2, x1), 1.0f), 1.0f);
        float roi_h = fmaxf(__fadd_rn(__fsub_rn(y2, y1), 1.0f), 1.0f);
        float bin_h = __fmul_rn(roi_h, R7);
        float bin_w = __fmul_rn(roi_w, R7);

        int ph = t / PW;
        int pw = t - ph * PW;
        float fph = (float)ph, fpw = (float)pw;

        int h0 = (int)fminf(fmaxf(__fadd_rn(floorf(__fmul_rn(fph, bin_h)), y1), 0.0f), (float)FH);
        int h1 = (int)fminf(fmaxf(__fadd_rn(ceilf(__fmul_rn(__fadd_rn(fph, 1.0f), bin_h)), y1), 0.0f), (float)FH);
        int w0 = (int)fminf(fmaxf(__fadd_rn(floorf(__fmul_rn(fpw, bin_w)), x1), 0.0f), (float)FW);
        int w1 = (int)fminf(fmaxf(__fadd_rn(ceilf(__fmul_rn(__fadd_rn(fpw, 1.0f), bin_w)), x1), 0.0f), (float)FW);

        unsigned mh = 0, mw = 0;
#pragma unroll
        for (int d = 0; d < 4; ++d) {
            mh |= (h0 + d < h1) ? (1u << d) : 0u;
            mw |= (w0 + d < w1) ? (1u << d) : 0u;
        }
        unsigned mask = 0;
#pragma unroll
        for (int d = 0; d < 4; ++d)
            mask |= ((mh >> d) & 1u) ? (mw << (4 * d)) : 0u;

        sbinoff4[t] = (h0 * FW + w0) * (NCH / 4);
        smask[t]    = mask;
        if (t == 0) bofs4 = roib[n] * (HW * NCH / 4);
    }
    __syncthreads();

    // lane covers 4 consecutive channels via float4 (channels contiguous in
    // transposed layout). Mask tests + load issue amortized over 4 outputs;
    // 4 independent fmax chains per lane; up to 16 independent LDG.128.
    const float4* __restrict__ fb = g_feat_t4 + bofs4 + (c0 >> 2) + lane;

    for (int bin = wid; bin < BINS; bin += 8) {
        const unsigned mask = smask[bin];
        const float4* __restrict__ f = fb + sbinoff4[bin];
        float4 m = make_float4(-INFINITY, -INFINITY, -INFINITY, -INFINITY);
#pragma unroll
        for (int dh = 0; dh < 4; ++dh) {
#pragma unroll
            for (int dw = 0; dw < 4; ++dw) {
                if (mask & (1u << (dh * 4 + dw))) {
                    float4 v = f[(dh * FW + dw) * (NCH / 4)];
                    m.x = fmaxf(m.x, v.x);
                    m.y = fmaxf(m.y, v.y);
                    m.z = fmaxf(m.z, v.z);
                    m.w = fmaxf(m.w, v.w);
                }
            }
        }
        if (mask == 0u) m = make_float4(0.f, 0.f, 0.f, 0.f);  // empty bin -> 0
        const int cb = lane * 4;
        so[(cb + 0) * BINS + bin] = m.x;
        so[(cb + 1) * BINS + bin] = m.y;
        so[(cb + 2) * BINS + bin] = m.z;
        so[(cb + 3) * BINS + bin] = m.w;
    }
    __syncthreads();

    // Block's output region is contiguous: coalesced float4 flush.
    // (6272 floats per block region => 16B-multiple offsets from d_out.)
    float4* __restrict__ op = (float4*)(out + n * TOTAL + c0 * BINS);
    const float4* __restrict__ sp = (const float4*)so;
#pragma unroll
    for (int e = t; e < CG * BINS / 4; e += 256)
        op[e] = sp[e];
}

extern "C" void kernel_launch(void* const* d_in, const int* in_sizes, int n_in,
                              void* d_out, int out_size)
{
    const float* feat = (const float*)d_in[0];
    const float* rois = (const float*)d_in[1];
    const int*   rb   = (const int*)d_in[2];
    float*       out  = (float*)d_out;

    dim3 tg((HW + 31) / 32, NCH / 32, NB);   // (46, 8, 4)
    dim3 tb(32, 8);
    transpose_kernel<<<tg, tb>>>(feat);

    dim3 grid(NCGRP, 256);                   // (2, 256)
    roipool2_kernel<<<grid, 256>>>(rois, rb, out);
}